// round 8
// baseline (speedup 1.0000x reference)
#include <cuda_runtime.h>

// ---------------------------------------------------------------------------
// Average_Model_fwRF: out[b] = bias + sum_f feats[b,f] * W[f]
// Collapses to out[b] = bias + sum_e input[b,e] * coef[e], coef batch-
// independent (347,240 floats, ~1.39 MB, L2-resident). Fast per-layer-block
// setup kernel builds coef; main kernel streams ~711 MB once. HBM-bound.
// ---------------------------------------------------------------------------

#define NB       512
#define NUNITS   18
#define COEF_TOT 347240

// per-layer element counts (C*H*H for conv, C for fc)
__constant__ int c_elems[8]    = {46656, 139968, 64896, 43264, 43264, 4096, 4096, 1000};
// coef buffer offsets (prefix sums of c_elems)
__constant__ int c_coef_off[9] = {0, 46656, 186624, 251520, 294784, 338048, 342144, 346240, 347240};
// work decomposition for reduce: 18 units per batch (chunks divide elems exactly)
__constant__ int c_unit_layer[NUNITS] = {0,0, 1,1,1,1,1,1, 2,2,2, 3,3, 4,4, 5, 6, 7};
__constant__ int c_unit_sub[NUNITS]   = {0,1, 0,1,2,3,4,5, 0,1,2, 0,1, 0,1, 0, 0, 0};
__constant__ int c_chunk[8]           = {23328, 23328, 21632, 21632, 21632, 4096, 4096, 1000};
// build kernel: per-layer block ranges (256 threads/block, 1 elem/thread)
// blocks: L0 183, L1 547, L2 254, L3 169, L4 169, L5 16, L6 16, L7 4, bias 2
__constant__ int c_bstart[9] = {0, 183, 730, 984, 1153, 1322, 1338, 1354, 1358};
#define BUILD_BLOCKS 1360

// batch-independent coefficient tensor (~1.39 MB)
__device__ float g_coef[COEF_TOT];

// idx buffers may be int32 (JAX x64-disabled downcast) or genuine int64.
// For little-endian int64 values < 4096 the odd 32-bit words are all zero;
// an int32 sorted-unique list has word[1] = idx[1] >= 1.
__device__ __forceinline__ int idx_is_i64(const int* w) {
    return (w[1] == 0) & (w[3] == 0) & (w[5] == 0);
}
__device__ __forceinline__ int idx_get(const int* w, int k, int is64) {
    return is64 ? w[2 * k] : w[k];
}

template<int P>
__device__ __forceinline__ float conv_coef(int local,
                                           const float* __restrict__ W, int woff,
                                           const float* __restrict__ mass)
{
    int ch = local / P;              // compile-time divisor -> mul-by-reciprocal
    int px = local - ch * P;
    return W[woff + ch] * mass[px];
}

// ---------------------------------------------------------------------------
// Setup: build coefficients + seed output with bias.
// Layer is determined by block index -> compile-time pixel divisor.
// ---------------------------------------------------------------------------
__global__ __launch_bounds__(256)
void build_coef_kernel(
    const float* __restrict__ m0, const float* __restrict__ m1,
    const float* __restrict__ m2, const float* __restrict__ m3,
    const float* __restrict__ m4,
    const float* __restrict__ W,  const float* __restrict__ mfc,
    const int* __restrict__ idx0, const int* __restrict__ idx1,
    const float* __restrict__ bias, float* __restrict__ out)
{
    int blk = blockIdx.x;

    // bias-seed blocks
    if (blk >= c_bstart[8]) {
        int t = (blk - c_bstart[8]) * 256 + threadIdx.x;
        if (t < NB) out[t] = bias[0];
        return;
    }

    // find layer (8 compares, unrolled)
    int layer = 0;
    #pragma unroll
    for (int l = 1; l < 8; ++l)
        if (blk >= c_bstart[l]) layer = l;

    int local = (blk - c_bstart[layer]) * 256 + threadIdx.x;
    if (local >= c_elems[layer]) return;

    float v;
    switch (layer) {
        case 0: v = conv_coef<729>(local, W, 0,   m0); break;
        case 1: v = conv_coef<729>(local, W, 64,  m1); break;
        case 2: v = conv_coef<169>(local, W, 256, m2); break;
        case 3: v = conv_coef<169>(local, W, 640, m3); break;
        case 4: v = conv_coef<169>(local, W, 896, m4); break;
        case 5: case 6: {
            const int* idx = (layer == 5) ? idx0 : idx1;
            int woff = (layer == 5) ? 1152 : 2176;
            int is64 = idx_is_i64(idx);
            float s = mfc[0];
            v = 0.0f;
            int lo = 0, hi = 1023;
            while (lo <= hi) {
                int mid = (lo + hi) >> 1;
                int t = idx_get(idx, mid, is64);
                if (t == local) { v = W[woff + mid] * s; break; }
                if (t < local) lo = mid + 1; else hi = mid - 1;
            }
            break;
        }
        default: v = W[3200 + local] * mfc[0]; break;
    }
    g_coef[c_coef_off[layer] + local] = v;
}

// ---------------------------------------------------------------------------
// Main: streaming weighted reduction. One block = one (batch, chunk) unit.
// MLP=2 body (best measured); full occupancy via launch_bounds(256, 8).
// ---------------------------------------------------------------------------
__global__ __launch_bounds__(256, 8)
void reduce_kernel(
    const float* __restrict__ f0, const float* __restrict__ f1,
    const float* __restrict__ f2, const float* __restrict__ f3,
    const float* __restrict__ f4,
    const float* __restrict__ fc0, const float* __restrict__ fc1,
    const float* __restrict__ fc2,
    float* __restrict__ out)
{
    int unit  = blockIdx.x % NUNITS;
    int batch = blockIdx.x / NUNITS;

    int layer = c_unit_layer[unit];
    int sub   = c_unit_sub[unit];
    int elems = c_elems[layer];
    int chunk = c_chunk[layer];

    const float* bases[8] = {f0, f1, f2, f3, f4, fc0, fc1, fc2};

    const float4* __restrict__ d =
        reinterpret_cast<const float4*>(bases[layer] + (size_t)batch * elems + (size_t)sub * chunk);
    const float4* __restrict__ cf =
        reinterpret_cast<const float4*>(g_coef + c_coef_off[layer] + sub * chunk);

    int n4 = chunk >> 2;            // float4 count
    int n4_main = n4 & ~511;        // multiple of 2*256 for the unrolled body

    float acc0 = 0.0f, acc1 = 0.0f;

    for (int i = threadIdx.x; i < n4_main; i += 512) {
        float4 x0 = __ldg(d + i);
        float4 c0 = __ldg(cf + i);
        float4 x1 = __ldg(d + i + 256);
        float4 c1 = __ldg(cf + i + 256);
        acc0 = fmaf(x0.x, c0.x, acc0);
        acc0 = fmaf(x0.y, c0.y, acc0);
        acc0 = fmaf(x0.z, c0.z, acc0);
        acc0 = fmaf(x0.w, c0.w, acc0);
        acc1 = fmaf(x1.x, c1.x, acc1);
        acc1 = fmaf(x1.y, c1.y, acc1);
        acc1 = fmaf(x1.z, c1.z, acc1);
        acc1 = fmaf(x1.w, c1.w, acc1);
    }
    for (int i = n4_main + threadIdx.x; i < n4; i += 256) {
        float4 x = __ldg(d + i);
        float4 c = __ldg(cf + i);
        acc0 = fmaf(x.x, c.x, acc0);
        acc0 = fmaf(x.y, c.y, acc0);
        acc0 = fmaf(x.z, c.z, acc0);
        acc0 = fmaf(x.w, c.w, acc0);
    }

    float acc = acc0 + acc1;

    #pragma unroll
    for (int o = 16; o; o >>= 1)
        acc += __shfl_xor_sync(0xffffffffu, acc, o);

    __shared__ float sred[8];
    int w = threadIdx.x >> 5;
    if ((threadIdx.x & 31) == 0) sred[w] = acc;
    __syncthreads();

    if (threadIdx.x < 8) {
        float v = sred[threadIdx.x];
        #pragma unroll
        for (int o = 4; o; o >>= 1)
            v += __shfl_xor_sync(0xffu, v, o);
        if (threadIdx.x == 0)
            atomicAdd(&out[batch], v);
    }
}

// ---------------------------------------------------------------------------
// Launch: identify inputs by element count (duplicates by appearance order;
// mass0==mass1 and mass2==mass3==mass4 exactly, so mass order is moot).
// ---------------------------------------------------------------------------
extern "C" void kernel_launch(void* const* d_in, const int* in_sizes, int n_in,
                              void* d_out, int out_size)
{
    const float *fm[5] = {0,0,0,0,0};
    const float *ms[5] = {0,0,0,0,0};
    const float *fcp[3] = {0,0,0};
    const float *Wp = 0, *bp = 0, *mfcp = 0;
    const int *ix[2] = {0,0};

    int n729 = 0, n169 = 0, n22m = 0, nfc = 0, n1 = 0, nidx = 0;

    for (int i = 0; i < n_in; ++i) {
        int s = in_sizes[i];
        const void* p = d_in[i];
        switch (s) {
            case 23887872: fm[0] = (const float*)p; break;            // 512*64*27*27
            case 71663616: fm[1] = (const float*)p; break;            // 512*192*27*27
            case 33226752: fm[2] = (const float*)p; break;            // 512*384*13*13
            case 22151168: fm[3 + (n22m++)] = (const float*)p; break; // fmap3, fmap4
            case 2097152:  fcp[nfc++] = (const float*)p; break;       // fc0, fc1
            case 512000:   fcp[2] = (const float*)p; break;           // fc2
            case 729:      ms[n729++] = (const float*)p; break;       // mass0, mass1
            case 169:      ms[2 + (n169++)] = (const float*)p; break; // mass2..4
            case 1024:     ix[nidx++] = (const int*)p; break;         // idx0, idx1
            case 4200:     Wp = (const float*)p; break;
            case 1:
                if (n1 == 0) mfcp = (const float*)p; else bp = (const float*)p;
                ++n1;
                break;
            default: break;
        }
    }

    float* out = (float*)d_out;

    build_coef_kernel<<<BUILD_BLOCKS, 256>>>(ms[0], ms[1], ms[2], ms[3], ms[4],
                                             Wp, mfcp, ix[0], ix[1], bp, out);

    reduce_kernel<<<NB * NUNITS, 256>>>(fm[0], fm[1], fm[2], fm[3], fm[4],
                                        fcp[0], fcp[1], fcp[2], out);
}

// round 9
// speedup vs baseline: 1.1200x; 1.1200x over previous
#include <cuda_runtime.h>

// ---------------------------------------------------------------------------
// Average_Model_fwRF: out[b] = bias + sum_f feats[b,f] * W[f]
// Collapses to out[b] = bias + sum_e input[b,e] * coef[e], coef batch-
// independent (347,240 floats, ~1.39 MB, L2-resident). Fast per-layer-block
// setup kernel builds coef; main kernel streams ~711 MB once with
// streaming (evict-first) loads so the fmap stream does not thrash the
// L2-resident coef tensor. HBM-bound.
// ---------------------------------------------------------------------------

#define NB       512
#define NUNITS   18
#define COEF_TOT 347240

// per-layer element counts (C*H*H for conv, C for fc)
__constant__ int c_elems[8]    = {46656, 139968, 64896, 43264, 43264, 4096, 4096, 1000};
// coef buffer offsets (prefix sums of c_elems)
__constant__ int c_coef_off[9] = {0, 46656, 186624, 251520, 294784, 338048, 342144, 346240, 347240};
// work decomposition for reduce: 18 units per batch (chunks divide elems exactly)
__constant__ int c_unit_layer[NUNITS] = {0,0, 1,1,1,1,1,1, 2,2,2, 3,3, 4,4, 5, 6, 7};
__constant__ int c_unit_sub[NUNITS]   = {0,1, 0,1,2,3,4,5, 0,1,2, 0,1, 0,1, 0, 0, 0};
__constant__ int c_chunk[8]           = {23328, 23328, 21632, 21632, 21632, 4096, 4096, 1000};
// build kernel: per-layer block ranges (256 threads/block, 1 elem/thread)
__constant__ int c_bstart[9] = {0, 183, 730, 984, 1153, 1322, 1338, 1354, 1358};
#define BUILD_BLOCKS 1360

// batch-independent coefficient tensor (~1.39 MB)
__device__ float g_coef[COEF_TOT];

// idx buffers may be int32 (JAX x64-disabled downcast) or genuine int64.
// For little-endian int64 values < 4096 the odd 32-bit words are all zero;
// an int32 sorted-unique list has word[1] = idx[1] >= 1.
__device__ __forceinline__ int idx_is_i64(const int* w) {
    return (w[1] == 0) & (w[3] == 0) & (w[5] == 0);
}
__device__ __forceinline__ int idx_get(const int* w, int k, int is64) {
    return is64 ? w[2 * k] : w[k];
}

template<int P>
__device__ __forceinline__ float conv_coef(int local,
                                           const float* __restrict__ W, int woff,
                                           const float* __restrict__ mass)
{
    int ch = local / P;              // compile-time divisor -> mul-by-reciprocal
    int px = local - ch * P;
    return W[woff + ch] * mass[px];
}

// ---------------------------------------------------------------------------
// Setup: build coefficients + seed output with bias.
// Layer is determined by block index -> compile-time pixel divisor.
// ---------------------------------------------------------------------------
__global__ __launch_bounds__(256)
void build_coef_kernel(
    const float* __restrict__ m0, const float* __restrict__ m1,
    const float* __restrict__ m2, const float* __restrict__ m3,
    const float* __restrict__ m4,
    const float* __restrict__ W,  const float* __restrict__ mfc,
    const int* __restrict__ idx0, const int* __restrict__ idx1,
    const float* __restrict__ bias, float* __restrict__ out)
{
    int blk = blockIdx.x;

    // bias-seed blocks
    if (blk >= c_bstart[8]) {
        int t = (blk - c_bstart[8]) * 256 + threadIdx.x;
        if (t < NB) out[t] = bias[0];
        return;
    }

    // find layer (8 compares, unrolled)
    int layer = 0;
    #pragma unroll
    for (int l = 1; l < 8; ++l)
        if (blk >= c_bstart[l]) layer = l;

    int local = (blk - c_bstart[layer]) * 256 + threadIdx.x;
    if (local >= c_elems[layer]) return;

    float v;
    switch (layer) {
        case 0: v = conv_coef<729>(local, W, 0,   m0); break;
        case 1: v = conv_coef<729>(local, W, 64,  m1); break;
        case 2: v = conv_coef<169>(local, W, 256, m2); break;
        case 3: v = conv_coef<169>(local, W, 640, m3); break;
        case 4: v = conv_coef<169>(local, W, 896, m4); break;
        case 5: case 6: {
            const int* idx = (layer == 5) ? idx0 : idx1;
            int woff = (layer == 5) ? 1152 : 2176;
            int is64 = idx_is_i64(idx);
            float s = mfc[0];
            v = 0.0f;
            int lo = 0, hi = 1023;
            while (lo <= hi) {
                int mid = (lo + hi) >> 1;
                int t = idx_get(idx, mid, is64);
                if (t == local) { v = W[woff + mid] * s; break; }
                if (t < local) lo = mid + 1; else hi = mid - 1;
            }
            break;
        }
        default: v = W[3200 + local] * mfc[0]; break;
    }
    g_coef[c_coef_off[layer] + local] = v;
}

// ---------------------------------------------------------------------------
// Main: streaming weighted reduction. One block = one (batch, chunk) unit.
// fmap loads use __ldcs (evict-first) so the once-through stream does not
// evict the L2-resident coef tensor; coef loads use __ldg.
// ---------------------------------------------------------------------------
__global__ __launch_bounds__(256)
void reduce_kernel(
    const float* __restrict__ f0, const float* __restrict__ f1,
    const float* __restrict__ f2, const float* __restrict__ f3,
    const float* __restrict__ f4,
    const float* __restrict__ fc0, const float* __restrict__ fc1,
    const float* __restrict__ fc2,
    float* __restrict__ out)
{
    int unit  = blockIdx.x % NUNITS;
    int batch = blockIdx.x / NUNITS;

    int layer = c_unit_layer[unit];
    int sub   = c_unit_sub[unit];
    int elems = c_elems[layer];
    int chunk = c_chunk[layer];

    const float* bases[8] = {f0, f1, f2, f3, f4, fc0, fc1, fc2};

    const float4* __restrict__ d =
        reinterpret_cast<const float4*>(bases[layer] + (size_t)batch * elems + (size_t)sub * chunk);
    const float4* __restrict__ cf =
        reinterpret_cast<const float4*>(g_coef + c_coef_off[layer] + sub * chunk);

    int n4 = chunk >> 2;            // float4 count
    int n4_main = n4 & ~511;        // multiple of 2*256 for the unrolled body

    float acc0 = 0.0f, acc1 = 0.0f;

    for (int i = threadIdx.x; i < n4_main; i += 512) {
        float4 x0 = __ldcs(d + i);         // streaming: evict-first
        float4 c0 = __ldg(cf + i);         // hot: keep in L2
        float4 x1 = __ldcs(d + i + 256);
        float4 c1 = __ldg(cf + i + 256);
        acc0 = fmaf(x0.x, c0.x, acc0);
        acc0 = fmaf(x0.y, c0.y, acc0);
        acc0 = fmaf(x0.z, c0.z, acc0);
        acc0 = fmaf(x0.w, c0.w, acc0);
        acc1 = fmaf(x1.x, c1.x, acc1);
        acc1 = fmaf(x1.y, c1.y, acc1);
        acc1 = fmaf(x1.z, c1.z, acc1);
        acc1 = fmaf(x1.w, c1.w, acc1);
    }
    for (int i = n4_main + threadIdx.x; i < n4; i += 256) {
        float4 x = __ldcs(d + i);
        float4 c = __ldg(cf + i);
        acc0 = fmaf(x.x, c.x, acc0);
        acc0 = fmaf(x.y, c.y, acc0);
        acc0 = fmaf(x.z, c.z, acc0);
        acc0 = fmaf(x.w, c.w, acc0);
    }

    float acc = acc0 + acc1;

    #pragma unroll
    for (int o = 16; o; o >>= 1)
        acc += __shfl_xor_sync(0xffffffffu, acc, o);

    __shared__ float sred[8];
    int w = threadIdx.x >> 5;
    if ((threadIdx.x & 31) == 0) sred[w] = acc;
    __syncthreads();

    if (threadIdx.x < 8) {
        float v = sred[threadIdx.x];
        #pragma unroll
        for (int o = 4; o; o >>= 1)
            v += __shfl_xor_sync(0xffu, v, o);
        if (threadIdx.x == 0)
            atomicAdd(&out[batch], v);
    }
}

// ---------------------------------------------------------------------------
// Launch: identify inputs by element count (duplicates by appearance order;
// mass0==mass1 and mass2==mass3==mass4 exactly, so mass order is moot).
// ---------------------------------------------------------------------------
extern "C" void kernel_launch(void* const* d_in, const int* in_sizes, int n_in,
                              void* d_out, int out_size)
{
    const float *fm[5] = {0,0,0,0,0};
    const float *ms[5] = {0,0,0,0,0};
    const float *fcp[3] = {0,0,0};
    const float *Wp = 0, *bp = 0, *mfcp = 0;
    const int *ix[2] = {0,0};

    int n729 = 0, n169 = 0, n22m = 0, nfc = 0, n1 = 0, nidx = 0;

    for (int i = 0; i < n_in; ++i) {
        int s = in_sizes[i];
        const void* p = d_in[i];
        switch (s) {
            case 23887872: fm[0] = (const float*)p; break;            // 512*64*27*27
            case 71663616: fm[1] = (const float*)p; break;            // 512*192*27*27
            case 33226752: fm[2] = (const float*)p; break;            // 512*384*13*13
            case 22151168: fm[3 + (n22m++)] = (const float*)p; break; // fmap3, fmap4
            case 2097152:  fcp[nfc++] = (const float*)p; break;       // fc0, fc1
            case 512000:   fcp[2] = (const float*)p; break;           // fc2
            case 729:      ms[n729++] = (const float*)p; break;       // mass0, mass1
            case 169:      ms[2 + (n169++)] = (const float*)p; break; // mass2..4
            case 1024:     ix[nidx++] = (const int*)p; break;         // idx0, idx1
            case 4200:     Wp = (const float*)p; break;
            case 1:
                if (n1 == 0) mfcp = (const float*)p; else bp = (const float*)p;
                ++n1;
                break;
            default: break;
        }
    }

    float* out = (float*)d_out;

    build_coef_kernel<<<BUILD_BLOCKS, 256>>>(ms[0], ms[1], ms[2], ms[3], ms[4],
                                             Wp, mfcp, ix[0], ix[1], bp, out);

    reduce_kernel<<<NB * NUNITS, 256>>>(fm[0], fm[1], fm[2], fm[3], fm[4],
                                        fcp[0], fcp[1], fcp[2], out);
}